// round 11
// baseline (speedup 1.0000x reference)
#include <cuda_runtime.h>
#include <cstdint>

// TriLinear: out[b,q,k] = (Q.w1)[b,q] + (K.w2)[b,k] + sum_d Q[b,q,d]*w3[d]*K[b,k,d]
// B=32, L=1024, D=768.
//
// tf32 mma.sync GEMM C = Q @ (w3 (*) K)^T, fp32 accumulate.
// - 128x128 block tile, 8 warps of 64x32, __launch_bounds__(256,2) ->
//   2 CTAs/SM (16 warps, 4 per SMSP) to hide LDS->cvt->MMA latency chains
//   (R10 profile: occ 12.5%, issue 35%, all pipes <40% => latency-bound)
// - cp.async 4-stage smem pipeline (raw fp32 in smem)
// - transform at fragment-load time: cvt.rna tf32 (+ w3 multiply for B)
// - rank-1 logit terms accumulated from raw fragment values (exactly-once:
//   wn==0 warps -> qlog, wm==0 warps -> klog), quad-shfl reduced, epilogue add.

#define L_DIM 1024
#define D_DIM 768
#define BM    128
#define BN    128
#define BK    16
#define NKT   (D_DIM / BK)     // 48
#define SKA   20               // padded row stride (floats): (20r+c)%32 is a
                               // permutation over r0..7 x c0..3 -> conflict-free
#define THREADS 256
#define NSTAGE  4

// ---- dynamic smem layout (bytes) ----
#define SM_W      0                        // w1|w2|w3 : 3*768*4 = 9216
#define SM_QLOG   9216                     // 128 floats
#define SM_KLOG   9728                     // 128 floats
#define SM_TILES  10752                    // 16B-aligned
#define A_STAGE_B (BM * SKA * 4)           // 10240
#define B_STAGE_B (BN * SKA * 4)           // 10240
#define STAGE_B   (A_STAGE_B + B_STAGE_B)  // 20480
#define SM_TOTAL  (SM_TILES + NSTAGE * STAGE_B)   // 92672  (x2 CTAs = 185KB/SM)

__device__ __forceinline__ float to_tf32(float x) {
    float y;
    asm("cvt.rna.tf32.f32 %0, %1;" : "=f"(y) : "f"(x));
    return y;
}

__device__ __forceinline__ void mma_tf32(float* d, const uint32_t* a, const uint32_t* b) {
    asm volatile(
        "mma.sync.aligned.m16n8k8.row.col.f32.tf32.tf32.f32 "
        "{%0,%1,%2,%3}, {%4,%5,%6,%7}, {%8,%9}, {%0,%1,%2,%3};\n"
        : "+f"(d[0]), "+f"(d[1]), "+f"(d[2]), "+f"(d[3])
        : "r"(a[0]), "r"(a[1]), "r"(a[2]), "r"(a[3]),
          "r"(b[0]), "r"(b[1]));
}

__device__ __forceinline__ uint32_t smem_u32(const void* p) {
    uint32_t a;
    asm("{ .reg .u64 t; cvta.to.shared.u64 t, %1; cvt.u32.u64 %0, t; }"
        : "=r"(a) : "l"(p));
    return a;
}

__device__ __forceinline__ void cpa16(uint32_t dst, const float* src) {
    asm volatile("cp.async.cg.shared.global [%0], [%1], 16;"
                 :: "r"(dst), "l"(src) : "memory");
}

__device__ __forceinline__ void cpa_commit() {
    asm volatile("cp.async.commit_group;" ::: "memory");
}

__device__ __forceinline__ void cpa_wait2() {
    asm volatile("cp.async.wait_group 2;" ::: "memory");
}

__global__ __launch_bounds__(THREADS, 2)
void trilinear_kernel(const float* __restrict__ Q,
                      const float* __restrict__ K,
                      const float* __restrict__ w1,
                      const float* __restrict__ w2,
                      const float* __restrict__ w3,
                      float* __restrict__ out)
{
    extern __shared__ char smc[];
    const uint32_t sb = smem_u32(smc);

    const int t    = threadIdx.x;
    const int lane = t & 31;
    const int wid  = t >> 5;
    const int wm   = wid >> 2;        // 0..1  (64-row slice)
    const int wn   = wid & 3;         // 0..3  (32-col slice)
    const int gr   = lane >> 2;       // 0..7
    const int gc   = lane & 3;        // 0..3

    const int bn = blockIdx.x, bm = blockIdx.y, bb = blockIdx.z;
    const float* Qb = Q + ((size_t)bb * L_DIM + (size_t)bm * BM) * D_DIM;
    const float* Kb = K + ((size_t)bb * L_DIM + (size_t)bn * BN) * D_DIM;

    // producer mapping: 4 consecutive threads cover one 16-float k-row
    const int prow = t >> 2;          // 0..63
    const int pkq  = t & 3;           // float4 index within the 16-float row

    // ---- stage w1/w2/w3 into smem (ordinary loads; visible after 1st sync) ----
    {
        float* wsm = (float*)(smc + SM_W);
        for (int i = t; i < D_DIM; i += THREADS) {
            wsm[i]             = __ldg(w1 + i);
            wsm[i + D_DIM]     = __ldg(w2 + i);
            wsm[i + 2 * D_DIM] = __ldg(w3 + i);
        }
    }

    auto issue_stage = [&](int c) {
        const int s = c & (NSTAGE - 1);
        const int koff = c * BK + pkq * 4;
        const uint32_t abase = sb + SM_TILES + s * STAGE_B;
        const uint32_t bbase = abase + A_STAGE_B;
        // A: rows prow, prow+64 ; B: rows prow, prow+64
        cpa16(abase + (uint32_t)(prow        * SKA + pkq * 4) * 4,
              Qb + (size_t)prow        * D_DIM + koff);
        cpa16(abase + (uint32_t)((prow + 64) * SKA + pkq * 4) * 4,
              Qb + (size_t)(prow + 64) * D_DIM + koff);
        cpa16(bbase + (uint32_t)(prow        * SKA + pkq * 4) * 4,
              Kb + (size_t)prow        * D_DIM + koff);
        cpa16(bbase + (uint32_t)((prow + 64) * SKA + pkq * 4) * 4,
              Kb + (size_t)(prow + 64) * D_DIM + koff);
    };

    float acc[4][4][4];
    #pragma unroll
    for (int i = 0; i < 4; i++)
        #pragma unroll
        for (int j = 0; j < 4; j++)
            #pragma unroll
            for (int k2 = 0; k2 < 4; k2++)
                acc[i][j][k2] = 0.f;

    float qp0[4], qp1[4], kp[4];      // logit partials (raw fp32)
    #pragma unroll
    for (int i = 0; i < 4; i++) { qp0[i] = 0.f; qp1[i] = 0.f; kp[i] = 0.f; }

    // ---- prologue: fill 3 stages ----
    issue_stage(0); cpa_commit();
    issue_stage(1); cpa_commit();
    issue_stage(2); cpa_commit();

    const float* wsm = (const float*)(smc + SM_W);

    // Pipeline invariant: stage c is the (c+1)-th committed group; before the
    // wait in iter c there are 3+c commits, so wait_group 2 -> stage c done.
    for (int c = 0; c < NKT; c++) {
        cpa_wait2();
        __syncthreads();              // stage-c data visible to all; also closes
                                      // iter c-1 reads of buffer (c-1)%4

        if (c + 3 < NKT) issue_stage(c + 3);
        cpa_commit();                 // commit every iter (empty groups are fine)

        const int s = c & (NSTAGE - 1);
        const float* Ab = (const float*)(smc + SM_TILES + s * STAGE_B);
        const float* Bb = (const float*)(smc + SM_TILES + s * STAGE_B + A_STAGE_B);

        #pragma unroll
        for (int ks = 0; ks < 2; ks++) {
            const int kb   = ks * 8;
            const int kg0  = c * BK + kb + gc;
            const float w1v0 = wsm[kg0],             w1v1 = wsm[kg0 + 4];
            const float w2v0 = wsm[D_DIM + kg0],     w2v1 = wsm[D_DIM + kg0 + 4];
            const float w3v0 = wsm[2 * D_DIM + kg0], w3v1 = wsm[2 * D_DIM + kg0 + 4];

            uint32_t afr[4][4], bfr[4][2];
            #pragma unroll
            for (int mf = 0; mf < 4; mf++) {
                const int mo = wm * 64 + mf * 16;
                const float a0 = Ab[(mo + gr    ) * SKA + kb + gc    ];
                const float a1 = Ab[(mo + gr + 8) * SKA + kb + gc    ];
                const float a2 = Ab[(mo + gr    ) * SKA + kb + gc + 4];
                const float a3 = Ab[(mo + gr + 8) * SKA + kb + gc + 4];
                if (wn == 0) {                      // exactly-once qlog coverage
                    qp0[mf] += a0 * w1v0 + a2 * w1v1;
                    qp1[mf] += a1 * w1v0 + a3 * w1v1;
                }
                afr[mf][0] = __float_as_uint(to_tf32(a0));
                afr[mf][1] = __float_as_uint(to_tf32(a1));
                afr[mf][2] = __float_as_uint(to_tf32(a2));
                afr[mf][3] = __float_as_uint(to_tf32(a3));
            }
            #pragma unroll
            for (int nf = 0; nf < 4; nf++) {
                const int no = wn * 32 + nf * 8;
                const float b0 = Bb[(no + gr) * SKA + kb + gc    ];
                const float b1 = Bb[(no + gr) * SKA + kb + gc + 4];
                if (wm == 0) {                      // exactly-once klog coverage
                    kp[nf] += b0 * w2v0 + b1 * w2v1;
                }
                bfr[nf][0] = __float_as_uint(to_tf32(b0 * w3v0));
                bfr[nf][1] = __float_as_uint(to_tf32(b1 * w3v1));
            }
            #pragma unroll
            for (int mf = 0; mf < 4; mf++)
                #pragma unroll
                for (int nf = 0; nf < 4; nf++)
                    mma_tf32(acc[mf][nf], afr[mf], bfr[nf]);
        }
    }

    // ---- reduce logit partials (quad shfl over lanes 4*gr + gc) ----
    float* qlog_s = (float*)(smc + SM_QLOG);
    float* klog_s = (float*)(smc + SM_KLOG);
    if (wn == 0) {
        #pragma unroll
        for (int mf = 0; mf < 4; mf++) {
            float v0 = qp0[mf], v1 = qp1[mf];
            v0 += __shfl_xor_sync(0xffffffffu, v0, 1);
            v0 += __shfl_xor_sync(0xffffffffu, v0, 2);
            v1 += __shfl_xor_sync(0xffffffffu, v1, 1);
            v1 += __shfl_xor_sync(0xffffffffu, v1, 2);
            if (gc == 0) {
                qlog_s[wm * 64 + mf * 16 + gr    ] = v0;
                qlog_s[wm * 64 + mf * 16 + gr + 8] = v1;
            }
        }
    }
    if (wm == 0) {
        #pragma unroll
        for (int nf = 0; nf < 4; nf++) {
            float v = kp[nf];
            v += __shfl_xor_sync(0xffffffffu, v, 1);
            v += __shfl_xor_sync(0xffffffffu, v, 2);
            if (gc == 0) klog_s[wn * 32 + nf * 8 + gr] = v;
        }
    }
    __syncthreads();

    // ---- epilogue: out = dot + qlog[q] + klog[k] ----
    float* Ob = out + ((size_t)bb * L_DIM + (size_t)bm * BM) * L_DIM + (size_t)bn * BN;
    #pragma unroll
    for (int mf = 0; mf < 4; mf++) {
        const int mo    = wm * 64 + mf * 16;
        const float ql0 = qlog_s[mo + gr];
        const float ql1 = qlog_s[mo + gr + 8];
        #pragma unroll
        for (int nf = 0; nf < 4; nf++) {
            const int no    = wn * 32 + nf * 8 + 2 * gc;
            const float kl0 = klog_s[no];
            const float kl1 = klog_s[no + 1];
            float2 v0, v1;
            v0.x = acc[mf][nf][0] + ql0 + kl0;
            v0.y = acc[mf][nf][1] + ql0 + kl1;
            v1.x = acc[mf][nf][2] + ql1 + kl0;
            v1.y = acc[mf][nf][3] + ql1 + kl1;
            *reinterpret_cast<float2*>(Ob + (size_t)(mo + gr    ) * L_DIM + no) = v0;
            *reinterpret_cast<float2*>(Ob + (size_t)(mo + gr + 8) * L_DIM + no) = v1;
        }
    }
}

extern "C" void kernel_launch(void* const* d_in, const int* in_sizes, int n_in,
                              void* d_out, int out_size)
{
    const float* Q  = (const float*)d_in[0];
    const float* K  = (const float*)d_in[1];
    const float* w1 = (const float*)d_in[2];
    const float* w2 = (const float*)d_in[3];
    const float* w3 = (const float*)d_in[4];

    // Unconditional (idempotent, deterministic, capture-safe) — no static guards.
    cudaFuncSetAttribute(trilinear_kernel,
                         cudaFuncAttributeMaxDynamicSharedMemorySize, SM_TOTAL);

    const int batches = in_sizes[0] / (L_DIM * D_DIM);   // 32
    dim3 grid(L_DIM / BN, L_DIM / BM, batches);          // (8, 8, 32)
    trilinear_kernel<<<grid, THREADS, SM_TOTAL>>>(Q, K, w1, w2, w3, (float*)d_out);
}

// round 12
// speedup vs baseline: 1.1861x; 1.1861x over previous
#include <cuda_runtime.h>
#include <cstdint>

// TriLinear: out[b,q,k] = (Q.w1)[b,q] + (K.w2)[b,k] + sum_d Q[b,q,d]*w3[d]*K[b,k,d]
// B=32, L=1024, D=768.
//
// Two-kernel plan (R11 post-mortem: mainloop was only ~20% MMA instructions):
//  1) prepass: At = tf32(Q), Bt = tf32(w3 (*) K) into __device__ scratch;
//     qlog = Q.w1, klog = K.w2 (fp32). Each element transformed ONCE instead
//     of ~32x in the GEMM fragments.
//  2) GEMM: 128x256 block, 8 warps of 64x64, cp.async 4-stage pipeline,
//     ldmatrix.x4 fragment loads (4x fewer shared-pipe instructions),
//     mainloop = LDSM + MMA only (~71% MMA). Epilogue adds qlog/klog.

#define L_DIM 1024
#define D_DIM 768
#define NROWS (32 * L_DIM)

// ---- device scratch (sanctioned: static __device__ arrays, no allocs) ----
__device__ float g_At[(size_t)NROWS * D_DIM];   // tf32(Q)
__device__ float g_Bt[(size_t)NROWS * D_DIM];   // tf32(w3*K)
__device__ float g_qlog[NROWS];
__device__ float g_klog[NROWS];

__device__ __forceinline__ float to_tf32(float x) {
    float y;
    asm("cvt.rna.tf32.f32 %0, %1;" : "=f"(y) : "f"(x));
    return y;
}

// ============================ pre-pass ============================
// One warp per row-pair (Q row r and K row r). 192 float4 per row, 6 per lane.
__global__ __launch_bounds__(256, 8)
void prepass_kernel(const float* __restrict__ Q,
                    const float* __restrict__ K,
                    const float* __restrict__ w1,
                    const float* __restrict__ w2,
                    const float* __restrict__ w3)
{
    const int wid  = threadIdx.x >> 5;
    const int lane = threadIdx.x & 31;
    const int row  = blockIdx.x * 8 + wid;          // 0..NROWS-1

    const float4* q4  = (const float4*)(Q + (size_t)row * D_DIM);
    const float4* k4  = (const float4*)(K + (size_t)row * D_DIM);
    const float4* w14 = (const float4*)w1;
    const float4* w24 = (const float4*)w2;
    const float4* w34 = (const float4*)w3;
    float4* a4 = (float4*)(g_At + (size_t)row * D_DIM);
    float4* b4 = (float4*)(g_Bt + (size_t)row * D_DIM);

    float qp = 0.f, kp = 0.f;
    #pragma unroll
    for (int j = 0; j < 6; j++) {
        const int idx = j * 32 + lane;              // 0..191
        float4 qv = q4[idx], kv = k4[idx];
        float4 v1 = w14[idx], v2 = w24[idx], v3 = w34[idx];
        qp += qv.x*v1.x + qv.y*v1.y + qv.z*v1.z + qv.w*v1.w;
        kp += kv.x*v2.x + kv.y*v2.y + kv.z*v2.z + kv.w*v2.w;
        float4 a, b;
        a.x = to_tf32(qv.x); a.y = to_tf32(qv.y);
        a.z = to_tf32(qv.z); a.w = to_tf32(qv.w);
        b.x = to_tf32(kv.x * v3.x); b.y = to_tf32(kv.y * v3.y);
        b.z = to_tf32(kv.z * v3.z); b.w = to_tf32(kv.w * v3.w);
        a4[idx] = a;
        b4[idx] = b;
    }
    #pragma unroll
    for (int off = 16; off; off >>= 1) {
        qp += __shfl_xor_sync(0xffffffffu, qp, off);
        kp += __shfl_xor_sync(0xffffffffu, kp, off);
    }
    if (lane == 0) {
        g_qlog[row] = qp;
        g_klog[row] = kp;
    }
}

// ============================ GEMM ============================
#define BM    128
#define BN    256
#define BK    16
#define NKT   (D_DIM / BK)     // 48
#define SKA   20               // padded row stride (floats); 8 rows x 80B hit
                               // all 32 banks -> LDSM conflict-free
#define THREADS 256
#define NSTAGE  4

#define SM_QLOG   0                        // 128 floats
#define SM_KLOG   512                      // 256 floats
#define SM_TILES  1536                     // 16B-aligned
#define A_STAGE_B (BM * SKA * 4)           // 10240
#define B_STAGE_B (BN * SKA * 4)           // 20480
#define STAGE_B   (A_STAGE_B + B_STAGE_B)  // 30720
#define SM_TOTAL  (SM_TILES + NSTAGE * STAGE_B)   // 124416

__device__ __forceinline__ void mma_tf32(float* d, const uint32_t* a, const uint32_t* b) {
    asm volatile(
        "mma.sync.aligned.m16n8k8.row.col.f32.tf32.tf32.f32 "
        "{%0,%1,%2,%3}, {%4,%5,%6,%7}, {%8,%9}, {%0,%1,%2,%3};\n"
        : "+f"(d[0]), "+f"(d[1]), "+f"(d[2]), "+f"(d[3])
        : "r"(a[0]), "r"(a[1]), "r"(a[2]), "r"(a[3]),
          "r"(b[0]), "r"(b[1]));
}

__device__ __forceinline__ void ldsm4(uint32_t* r, uint32_t a) {
    asm volatile("ldmatrix.sync.aligned.m8n8.x4.shared.b16 {%0,%1,%2,%3}, [%4];"
                 : "=r"(r[0]), "=r"(r[1]), "=r"(r[2]), "=r"(r[3]) : "r"(a));
}

__device__ __forceinline__ uint32_t smem_u32(const void* p) {
    uint32_t a;
    asm("{ .reg .u64 t; cvta.to.shared.u64 t, %1; cvt.u32.u64 %0, t; }"
        : "=r"(a) : "l"(p));
    return a;
}

__device__ __forceinline__ void cpa16(uint32_t dst, const float* src) {
    asm volatile("cp.async.cg.shared.global [%0], [%1], 16;"
                 :: "r"(dst), "l"(src) : "memory");
}

__device__ __forceinline__ void cpa_commit() {
    asm volatile("cp.async.commit_group;" ::: "memory");
}

__device__ __forceinline__ void cpa_wait2() {
    asm volatile("cp.async.wait_group 2;" ::: "memory");
}

__global__ __launch_bounds__(THREADS, 1)
void trilinear_gemm(float* __restrict__ out)
{
    extern __shared__ char smc[];
    const uint32_t sb = smem_u32(smc);

    const int t    = threadIdx.x;
    const int lane = t & 31;
    const int wid  = t >> 5;
    const int wm   = wid >> 2;        // 0..1  (64-row slice)
    const int wn   = wid & 3;         // 0..3  (64-col slice)
    const int gr   = lane >> 2;       // 0..7
    const int gc   = lane & 3;        // 0..3

    const int bn = blockIdx.x, bm = blockIdx.y, bb = blockIdx.z;
    const float* Ag = g_At + ((size_t)bb * L_DIM + (size_t)bm * BM) * D_DIM;
    const float* Bg = g_Bt + ((size_t)bb * L_DIM + (size_t)bn * BN) * D_DIM;

    // producer mapping: 4 consecutive threads cover one 16-float k-row
    const int prow = t >> 2;          // 0..63
    const int pkq  = t & 3;

    // ---- stage qlog/klog into smem (ordinary LDG; visible after 1st sync) ----
    {
        float* ql = (float*)(smc + SM_QLOG);
        float* kl = (float*)(smc + SM_KLOG);
        if (t < 128) ql[t] = g_qlog[bb * L_DIM + bm * BM + t];
        kl[t] = g_klog[bb * L_DIM + bn * BN + t];
    }

    auto issue_stage = [&](int c) {
        const int s = c & (NSTAGE - 1);
        const int koff = c * BK + pkq * 4;
        const uint32_t abase = sb + SM_TILES + s * STAGE_B;
        const uint32_t bbase = abase + A_STAGE_B;
        cpa16(abase + (uint32_t)(prow        * SKA + pkq * 4) * 4,
              Ag + (size_t)prow        * D_DIM + koff);
        cpa16(abase + (uint32_t)((prow + 64) * SKA + pkq * 4) * 4,
              Ag + (size_t)(prow + 64) * D_DIM + koff);
        #pragma unroll
        for (int i = 0; i < 4; i++) {
            const int r = prow + 64 * i;
            cpa16(bbase + (uint32_t)(r * SKA + pkq * 4) * 4,
                  Bg + (size_t)r * D_DIM + koff);
        }
    };

    float acc[4][8][4];
    #pragma unroll
    for (int i = 0; i < 4; i++)
        #pragma unroll
        for (int j = 0; j < 8; j++)
            #pragma unroll
            for (int k2 = 0; k2 < 4; k2++)
                acc[i][j][k2] = 0.f;

    // ---- ldmatrix per-lane base offsets (within a stage) ----
    // A tiles (x4): t0=(rows lo,+0) t1=(rows hi,+0) t2=(rows lo,+16B) t3=(hi,+16B)
    //   -> regs r0..r3 = a0,a1,a2,a3
    const int tA = lane >> 3, rA = lane & 7;
    const uint32_t aOff = (uint32_t)((wm * 64 + (tA & 1) * 8 + rA) * SKA) * 4
                        + (uint32_t)(tA >> 1) * 16;
    // B tiles (x4): t0=(n lo,+0) t1=(n lo,+16B) t2=(n hi,+0) t3=(n hi,+16B)
    //   -> regs r0,r1 = b0,b1 of nf=2p ; r2,r3 = b0,b1 of nf=2p+1
    const uint32_t bOff = (uint32_t)((wn * 64 + (tA >> 1) * 8 + rA) * SKA) * 4
                        + (uint32_t)(tA & 1) * 16;

    // ---- prologue: fill 3 stages ----
    issue_stage(0); cpa_commit();
    issue_stage(1); cpa_commit();
    issue_stage(2); cpa_commit();

    // Pipeline invariant: before the wait in iter c there are 3+c commits;
    // wait_group 2 -> stage c complete. Buffer (c+3)%4 == (c-1)%4 is only
    // refilled after the __syncthreads that closed iter c-1's reads.
    for (int c = 0; c < NKT; c++) {
        cpa_wait2();
        __syncthreads();

        if (c + 3 < NKT) issue_stage(c + 3);
        cpa_commit();

        const int s = c & (NSTAGE - 1);
        const uint32_t aBase = sb + SM_TILES + s * STAGE_B + aOff;
        const uint32_t bBase = sb + SM_TILES + s * STAGE_B + A_STAGE_B + bOff;

        #pragma unroll
        for (int ks = 0; ks < 2; ks++) {
            const uint32_t kbyte = (uint32_t)ks * 32;
            uint32_t afr[4][4], bfr[4][4];
            #pragma unroll
            for (int mf = 0; mf < 4; mf++)
                ldsm4(afr[mf], aBase + (uint32_t)(mf * 16 * SKA) * 4 + kbyte);
            #pragma unroll
            for (int p = 0; p < 4; p++)
                ldsm4(bfr[p], bBase + (uint32_t)(p * 16 * SKA) * 4 + kbyte);
            #pragma unroll
            for (int mf = 0; mf < 4; mf++)
                #pragma unroll
                for (int p = 0; p < 4; p++) {
                    mma_tf32(acc[mf][2 * p    ], afr[mf], &bfr[p][0]);
                    mma_tf32(acc[mf][2 * p + 1], afr[mf], &bfr[p][2]);
                }
        }
    }
    __syncthreads();   // logit smem written before loop; ensure visible (cheap)

    // ---- epilogue: out = dot + qlog[q] + klog[k] ----
    const float* qlog_s = (const float*)(smc + SM_QLOG);
    const float* klog_s = (const float*)(smc + SM_KLOG);
    float* Ob = out + ((size_t)bb * L_DIM + (size_t)bm * BM) * L_DIM + (size_t)bn * BN;
    #pragma unroll
    for (int mf = 0; mf < 4; mf++) {
        const int mo    = wm * 64 + mf * 16;
        const float ql0 = qlog_s[mo + gr];
        const float ql1 = qlog_s[mo + gr + 8];
        #pragma unroll
        for (int nf = 0; nf < 8; nf++) {
            const int no    = wn * 64 + nf * 8 + 2 * gc;
            const float kl0 = klog_s[no];
            const float kl1 = klog_s[no + 1];
            float2 v0, v1;
            v0.x = acc[mf][nf][0] + ql0 + kl0;
            v0.y = acc[mf][nf][1] + ql0 + kl1;
            v1.x = acc[mf][nf][2] + ql1 + kl0;
            v1.y = acc[mf][nf][3] + ql1 + kl1;
            *reinterpret_cast<float2*>(Ob + (size_t)(mo + gr    ) * L_DIM + no) = v0;
            *reinterpret_cast<float2*>(Ob + (size_t)(mo + gr + 8) * L_DIM + no) = v1;
        }
    }
}

extern "C" void kernel_launch(void* const* d_in, const int* in_sizes, int n_in,
                              void* d_out, int out_size)
{
    const float* Q  = (const float*)d_in[0];
    const float* K  = (const float*)d_in[1];
    const float* w1 = (const float*)d_in[2];
    const float* w2 = (const float*)d_in[3];
    const float* w3 = (const float*)d_in[4];

    cudaFuncSetAttribute(trilinear_gemm,
                         cudaFuncAttributeMaxDynamicSharedMemorySize, SM_TOTAL);

    prepass_kernel<<<NROWS / 8, 256>>>(Q, K, w1, w2, w3);

    dim3 grid(L_DIM / BN, L_DIM / BM, 32);   // (4, 8, 32)
    trilinear_gemm<<<grid, THREADS, SM_TOTAL>>>((float*)d_out);
}

// round 15
// speedup vs baseline: 1.1998x; 1.0115x over previous
#include <cuda_runtime.h>
#include <cstdint>

// TriLinear: out[b,q,k] = (Q.w1)[b,q] + (K.w2)[b,k] + sum_d Q[b,q,d]*w3[d]*K[b,k,d]
// B=32, L=1024, D=768.
//
// Two-kernel plan:
//  1) prepass: Bt = tf32(w3 (*) K) into __device__ scratch (96 MB);
//     qlog = Q.w1, klog = K.w2 (fp32).
//  2) GEMM: 128x128 block, 4 warps of 64x64, __launch_bounds__(128,2) ->
//     2 INDEPENDENT CTAs/SM (R12 evidence: tensor=49%, issue=12.8% with one
//     barrier-lockstepped CTA; two CTAs barrier independently and fill each
//     other's bubbles). cp.async 5-stage pipeline, ldmatrix.x4 fragments.
//     A streams RAW Q; cvt.rna applied to A fragments post-ldmatrix (same
//     values, same rounding -> bit-identical results to the 408us kernel).

#define L_DIM 1024
#define D_DIM 768
#define NROWS (32 * L_DIM)

// ---- device scratch (static __device__ arrays: no allocs) ----
__device__ float g_Bt[(size_t)NROWS * D_DIM];   // tf32(w3*K)  (96 MB)
__device__ float g_qlog[NROWS];
__device__ float g_klog[NROWS];

__device__ __forceinline__ float to_tf32(float x) {
    float y;
    asm("cvt.rna.tf32.f32 %0, %1;" : "=f"(y) : "f"(x));
    return y;
}

// ============================ pre-pass ============================
// One warp per row r: transforms K row, logits for Q row and K row.
__global__ __launch_bounds__(256, 8)
void prepass_kernel(const float* __restrict__ Q,
                    const float* __restrict__ K,
                    const float* __restrict__ w1,
                    const float* __restrict__ w2,
                    const float* __restrict__ w3)
{
    const int wid  = threadIdx.x >> 5;
    const int lane = threadIdx.x & 31;
    const int row  = blockIdx.x * 8 + wid;

    const float4* q4  = (const float4*)(Q + (size_t)row * D_DIM);
    const float4* k4  = (const float4*)(K + (size_t)row * D_DIM);
    const float4* w14 = (const float4*)w1;
    const float4* w24 = (const float4*)w2;
    const float4* w34 = (const float4*)w3;
    float4* b4 = (float4*)(g_Bt + (size_t)row * D_DIM);

    float qp = 0.f, kp = 0.f;
    #pragma unroll
    for (int j = 0; j < 6; j++) {
        const int idx = j * 32 + lane;              // 0..191
        float4 qv = q4[idx], kv = k4[idx];
        float4 v1 = w14[idx], v2 = w24[idx], v3 = w34[idx];
        qp += qv.x*v1.x + qv.y*v1.y + qv.z*v1.z + qv.w*v1.w;
        kp += kv.x*v2.x + kv.y*v2.y + kv.z*v2.z + kv.w*v2.w;
        float4 b;
        b.x = to_tf32(kv.x * v3.x); b.y = to_tf32(kv.y * v3.y);
        b.z = to_tf32(kv.z * v3.z); b.w = to_tf32(kv.w * v3.w);
        b4[idx] = b;
    }
    #pragma unroll
    for (int off = 16; off; off >>= 1) {
        qp += __shfl_xor_sync(0xffffffffu, qp, off);
        kp += __shfl_xor_sync(0xffffffffu, kp, off);
    }
    if (lane == 0) {
        g_qlog[row] = qp;
        g_klog[row] = kp;
    }
}

// ============================ GEMM ============================
#define BM    128
#define BN    128
#define BK    16
#define NKT   (D_DIM / BK)     // 48
#define SKA   20               // padded row stride (floats); 8 rows x 80B hit
                               // all 32 banks -> LDSM conflict-free
#define THREADS 128
#define NSTAGE  5

#define SM_QLOG   0                        // 128 floats
#define SM_KLOG   512                      // 128 floats
#define SM_TILES  1024                     // 16B-aligned
#define A_STAGE_B (BM * SKA * 4)           // 10240
#define B_STAGE_B (BN * SKA * 4)           // 10240
#define STAGE_B   (A_STAGE_B + B_STAGE_B)  // 20480
#define SM_TOTAL  (SM_TILES + NSTAGE * STAGE_B)   // 103424 (x2 CTAs = 207KB/SM)

__device__ __forceinline__ void mma_tf32(float* d, const uint32_t* a, const uint32_t* b) {
    asm volatile(
        "mma.sync.aligned.m16n8k8.row.col.f32.tf32.tf32.f32 "
        "{%0,%1,%2,%3}, {%4,%5,%6,%7}, {%8,%9}, {%0,%1,%2,%3};\n"
        : "+f"(d[0]), "+f"(d[1]), "+f"(d[2]), "+f"(d[3])
        : "r"(a[0]), "r"(a[1]), "r"(a[2]), "r"(a[3]),
          "r"(b[0]), "r"(b[1]));
}

__device__ __forceinline__ void ldsm4(uint32_t* r, uint32_t a) {
    asm volatile("ldmatrix.sync.aligned.m8n8.x4.shared.b16 {%0,%1,%2,%3}, [%4];"
                 : "=r"(r[0]), "=r"(r[1]), "=r"(r[2]), "=r"(r[3]) : "r"(a));
}

__device__ __forceinline__ uint32_t smem_u32(const void* p) {
    uint32_t a;
    asm("{ .reg .u64 t; cvta.to.shared.u64 t, %1; cvt.u32.u64 %0, t; }"
        : "=r"(a) : "l"(p));
    return a;
}

__device__ __forceinline__ void cpa16(uint32_t dst, const float* src) {
    asm volatile("cp.async.cg.shared.global [%0], [%1], 16;"
                 :: "r"(dst), "l"(src) : "memory");
}

__device__ __forceinline__ void cpa_commit() {
    asm volatile("cp.async.commit_group;" ::: "memory");
}

__device__ __forceinline__ void cpa_wait3() {
    asm volatile("cp.async.wait_group 3;" ::: "memory");
}

__global__ __launch_bounds__(THREADS, 2)
void trilinear_gemm(const float* __restrict__ Q, float* __restrict__ out)
{
    extern __shared__ char smc[];
    const uint32_t sb = smem_u32(smc);

    const int t    = threadIdx.x;
    const int lane = t & 31;
    const int wid  = t >> 5;          // 0..3
    const int wm   = wid >> 1;        // 0..1  (64-row slice)
    const int wn   = wid & 1;         // 0..1  (64-col slice)
    const int gr   = lane >> 2;       // 0..7
    const int gc   = lane & 3;        // 0..3

    const int bn = blockIdx.x, bm = blockIdx.y, bb = blockIdx.z;
    const float* Ag = Q    + ((size_t)bb * L_DIM + (size_t)bm * BM) * D_DIM;  // raw Q
    const float* Bg = g_Bt + ((size_t)bb * L_DIM + (size_t)bn * BN) * D_DIM;  // tf32(w3*K)

    // producer mapping: 4 consecutive threads cover one 16-float k-row
    const int prow = t >> 2;          // 0..31
    const int pkq  = t & 3;

    // ---- stage qlog/klog into smem (ordinary LDG; visible after 1st sync) ----
    {
        float* ql = (float*)(smc + SM_QLOG);
        float* kl = (float*)(smc + SM_KLOG);
        ql[t] = g_qlog[bb * L_DIM + bm * BM + t];
        kl[t] = g_klog[bb * L_DIM + bn * BN + t];
    }

    auto issue_stage = [&](int c) {
        const int s = c % NSTAGE;
        const int koff = c * BK + pkq * 4;
        const uint32_t abase = sb + SM_TILES + s * STAGE_B;
        const uint32_t bbase = abase + A_STAGE_B;
        #pragma unroll
        for (int i = 0; i < 4; i++) {
            const int r = prow + 32 * i;
            cpa16(abase + (uint32_t)(r * SKA + pkq * 4) * 4,
                  Ag + (size_t)r * D_DIM + koff);
            cpa16(bbase + (uint32_t)(r * SKA + pkq * 4) * 4,
                  Bg + (size_t)r * D_DIM + koff);
        }
    };

    float acc[4][8][4];
    #pragma unroll
    for (int i = 0; i < 4; i++)
        #pragma unroll
        for (int j = 0; j < 8; j++)
            #pragma unroll
            for (int k2 = 0; k2 < 4; k2++)
                acc[i][j][k2] = 0.f;

    // ---- ldmatrix per-lane base offsets (within a stage) ----
    // A (x4): t0=(rows lo,+0) t1=(rows hi,+0) t2=(rows lo,+16B) t3=(hi,+16B)
    //   -> regs r0..r3 = a0,a1,a2,a3
    const int tA = lane >> 3, rA = lane & 7;
    const uint32_t aOff = (uint32_t)((wm * 64 + (tA & 1) * 8 + rA) * SKA) * 4
                        + (uint32_t)(tA >> 1) * 16;
    // B (x4): t0=(n lo,+0) t1=(n lo,+16B) t2=(n hi,+0) t3=(n hi,+16B)
    //   -> r0,r1 = b0,b1 of nf=2p ; r2,r3 = b0,b1 of nf=2p+1
    const uint32_t bOff = (uint32_t)((wn * 64 + (tA >> 1) * 8 + rA) * SKA) * 4
                        + (uint32_t)(tA & 1) * 16;

    // ---- prologue: fill 4 of 5 stages ----
    issue_stage(0); cpa_commit();
    issue_stage(1); cpa_commit();
    issue_stage(2); cpa_commit();
    issue_stage(3); cpa_commit();

    // Invariant: before the wait in iter c there are 4+c commits; wait_group 3
    // -> stage c complete. issue_stage(c+4) writes buffer (c+4)%5 == (c-1)%5,
    // whose iter c-1 reads were closed by the __syncthreads at top of iter c.
    for (int c = 0; c < NKT; c++) {
        cpa_wait3();
        __syncthreads();

        if (c + 4 < NKT) issue_stage(c + 4);
        cpa_commit();

        const int s = c % NSTAGE;
        const uint32_t aBase = sb + SM_TILES + s * STAGE_B + aOff;
        const uint32_t bBase = sb + SM_TILES + s * STAGE_B + A_STAGE_B + bOff;

        #pragma unroll
        for (int ks = 0; ks < 2; ks++) {
            const uint32_t kbyte = (uint32_t)ks * 32;
            uint32_t afr[4][4], bfr[4][4];
            #pragma unroll
            for (int mf = 0; mf < 4; mf++) {
                ldsm4(afr[mf], aBase + (uint32_t)(mf * 16 * SKA) * 4 + kbyte);
                #pragma unroll
                for (int r = 0; r < 4; r++)    // A is raw fp32: round here
                    afr[mf][r] = __float_as_uint(to_tf32(__uint_as_float(afr[mf][r])));
            }
            #pragma unroll
            for (int p = 0; p < 4; p++)
                ldsm4(bfr[p], bBase + (uint32_t)(p * 16 * SKA) * 4 + kbyte);
            #pragma unroll
            for (int mf = 0; mf < 4; mf++)
                #pragma unroll
                for (int p = 0; p < 4; p++) {
                    mma_tf32(acc[mf][2 * p    ], afr[mf], &bfr[p][0]);
                    mma_tf32(acc[mf][2 * p + 1], afr[mf], &bfr[p][2]);
                }
        }
    }
    __syncthreads();

    // ---- epilogue: out = dot + qlog[q] + klog[k] ----
    const float* qlog_s = (const float*)(smc + SM_QLOG);
    const float* klog_s = (const float*)(smc + SM_KLOG);
    float* Ob = out + ((size_t)bb * L_DIM + (size_t)bm * BM) * L_DIM + (size_t)bn * BN;
    #pragma unroll
    for (int mf = 0; mf < 4; mf++) {
        const int mo    = wm * 64 + mf * 16;
        const float ql0 = qlog_s[mo + gr];
        const float ql1 = qlog_s[mo + gr + 8];
        #pragma unroll
        for (int nf = 0; nf < 8; nf++) {
            const int no    = wn * 64 + nf * 8 + 2 * gc;
            const float kl0 = klog_s[no];
            const float kl1 = klog_s[no + 1];
            float2 v0, v1;
            v0.x = acc[mf][nf][0] + ql0 + kl0;
            v0.y = acc[mf][nf][1] + ql0 + kl1;
            v1.x = acc[mf][nf][2] + ql1 + kl0;
            v1.y = acc[mf][nf][3] + ql1 + kl1;
            *reinterpret_cast<float2*>(Ob + (size_t)(mo + gr    ) * L_DIM + no) = v0;
            *reinterpret_cast<float2*>(Ob + (size_t)(mo + gr + 8) * L_DIM + no) = v1;
        }
    }
}

extern "C" void kernel_launch(void* const* d_in, const int* in_sizes, int n_in,
                              void* d_out, int out_size)
{
    const float* Q  = (const float*)d_in[0];
    const float* K  = (const float*)d_in[1];
    const float* w1 = (const float*)d_in[2];
    const float* w2 = (const float*)d_in[3];
    const float* w3 = (const float*)d_in[4];

    cudaFuncSetAttribute(trilinear_gemm,
                         cudaFuncAttributeMaxDynamicSharedMemorySize, SM_TOTAL);

    prepass_kernel<<<NROWS / 8, 256>>>(Q, K, w1, w2, w3);

    dim3 grid(L_DIM / BN, L_DIM / BM, 32);   // (8, 8, 32)
    trilinear_gemm<<<grid, THREADS, SM_TOTAL>>>(Q, (float*)d_out);
}

// round 16
// speedup vs baseline: 1.2038x; 1.0033x over previous
#include <cuda_runtime.h>
#include <cstdint>

// TriLinear: out[b,q,k] = (Q.w1)[b,q] + (K.w2)[b,k] + sum_d Q[b,q,d]*w3[d]*K[b,k,d]
// B=32, L=1024, D=768.
//
// Two-kernel plan:
//  1) prepass: Bt = tf32(w3 (*) K) into __device__ scratch (96 MB);
//     qlog = Q.w1, klog = K.w2 (fp32).
//  2) GEMM: 128x128 block, 4 warps of 64x64, 2 CTAs/SM, cp.async 5-stage.
//     R15 post-mortem: stalls were exposed LDSM->cvt chains in front of each
//     32-MMA burst (2x per tile). This version batches ALL 32 LDSMs of the
//     tile right after the barrier, cvt's A in place, then runs all 128 MMAs
//     back-to-back so ks1 fragment latency hides under ks0's MMA burst.

#define L_DIM 1024
#define D_DIM 768
#define NROWS (32 * L_DIM)

// ---- device scratch (static __device__ arrays: no allocs) ----
__device__ float g_Bt[(size_t)NROWS * D_DIM];   // tf32(w3*K)  (96 MB)
__device__ float g_qlog[NROWS];
__device__ float g_klog[NROWS];

__device__ __forceinline__ float to_tf32(float x) {
    float y;
    asm("cvt.rna.tf32.f32 %0, %1;" : "=f"(y) : "f"(x));
    return y;
}

// ============================ pre-pass ============================
__global__ __launch_bounds__(256, 8)
void prepass_kernel(const float* __restrict__ Q,
                    const float* __restrict__ K,
                    const float* __restrict__ w1,
                    const float* __restrict__ w2,
                    const float* __restrict__ w3)
{
    const int wid  = threadIdx.x >> 5;
    const int lane = threadIdx.x & 31;
    const int row  = blockIdx.x * 8 + wid;

    const float4* q4  = (const float4*)(Q + (size_t)row * D_DIM);
    const float4* k4  = (const float4*)(K + (size_t)row * D_DIM);
    const float4* w14 = (const float4*)w1;
    const float4* w24 = (const float4*)w2;
    const float4* w34 = (const float4*)w3;
    float4* b4 = (float4*)(g_Bt + (size_t)row * D_DIM);

    float qp = 0.f, kp = 0.f;
    #pragma unroll
    for (int j = 0; j < 6; j++) {
        const int idx = j * 32 + lane;              // 0..191
        float4 qv = q4[idx], kv = k4[idx];
        float4 v1 = w14[idx], v2 = w24[idx], v3 = w34[idx];
        qp += qv.x*v1.x + qv.y*v1.y + qv.z*v1.z + qv.w*v1.w;
        kp += kv.x*v2.x + kv.y*v2.y + kv.z*v2.z + kv.w*v2.w;
        float4 b;
        b.x = to_tf32(kv.x * v3.x); b.y = to_tf32(kv.y * v3.y);
        b.z = to_tf32(kv.z * v3.z); b.w = to_tf32(kv.w * v3.w);
        b4[idx] = b;
    }
    #pragma unroll
    for (int off = 16; off; off >>= 1) {
        qp += __shfl_xor_sync(0xffffffffu, qp, off);
        kp += __shfl_xor_sync(0xffffffffu, kp, off);
    }
    if (lane == 0) {
        g_qlog[row] = qp;
        g_klog[row] = kp;
    }
}

// ============================ GEMM ============================
#define BM    128
#define BN    128
#define BK    16
#define NKT   (D_DIM / BK)     // 48
#define SKA   20               // padded row stride (floats); 8 rows x 80B hit
                               // all 32 banks -> LDSM conflict-free
#define THREADS 128
#define NSTAGE  5

#define SM_QLOG   0                        // 128 floats
#define SM_KLOG   512                      // 128 floats
#define SM_TILES  1024                     // 16B-aligned
#define A_STAGE_B (BM * SKA * 4)           // 10240
#define B_STAGE_B (BN * SKA * 4)           // 10240
#define STAGE_B   (A_STAGE_B + B_STAGE_B)  // 20480
#define SM_TOTAL  (SM_TILES + NSTAGE * STAGE_B)   // 103424 (x2 CTAs = 207KB/SM)

__device__ __forceinline__ void mma_tf32(float* d, const uint32_t* a, const uint32_t* b) {
    asm volatile(
        "mma.sync.aligned.m16n8k8.row.col.f32.tf32.tf32.f32 "
        "{%0,%1,%2,%3}, {%4,%5,%6,%7}, {%8,%9}, {%0,%1,%2,%3};\n"
        : "+f"(d[0]), "+f"(d[1]), "+f"(d[2]), "+f"(d[3])
        : "r"(a[0]), "r"(a[1]), "r"(a[2]), "r"(a[3]),
          "r"(b[0]), "r"(b[1]));
}

__device__ __forceinline__ void ldsm4(uint32_t* r, uint32_t a) {
    asm volatile("ldmatrix.sync.aligned.m8n8.x4.shared.b16 {%0,%1,%2,%3}, [%4];"
                 : "=r"(r[0]), "=r"(r[1]), "=r"(r[2]), "=r"(r[3]) : "r"(a));
}

__device__ __forceinline__ uint32_t smem_u32(const void* p) {
    uint32_t a;
    asm("{ .reg .u64 t; cvta.to.shared.u64 t, %1; cvt.u32.u64 %0, t; }"
        : "=r"(a) : "l"(p));
    return a;
}

__device__ __forceinline__ void cpa16(uint32_t dst, const float* src) {
    asm volatile("cp.async.cg.shared.global [%0], [%1], 16;"
                 :: "r"(dst), "l"(src) : "memory");
}

__device__ __forceinline__ void cpa_commit() {
    asm volatile("cp.async.commit_group;" ::: "memory");
}

__device__ __forceinline__ void cpa_wait3() {
    asm volatile("cp.async.wait_group 3;" ::: "memory");
}

__global__ __launch_bounds__(THREADS, 2)
void trilinear_gemm(const float* __restrict__ Q, float* __restrict__ out)
{
    extern __shared__ char smc[];
    const uint32_t sb = smem_u32(smc);

    const int t    = threadIdx.x;
    const int lane = t & 31;
    const int wid  = t >> 5;          // 0..3
    const int wm   = wid >> 1;        // 0..1  (64-row slice)
    const int wn   = wid & 1;         // 0..1  (64-col slice)
    const int gr   = lane >> 2;       // 0..7
    const int gc   = lane & 3;        // 0..3

    const int bn = blockIdx.x, bm = blockIdx.y, bb = blockIdx.z;
    const float* Ag = Q    + ((size_t)bb * L_DIM + (size_t)bm * BM) * D_DIM;  // raw Q
    const float* Bg = g_Bt + ((size_t)bb * L_DIM + (size_t)bn * BN) * D_DIM;  // tf32(w3*K)

    // producer mapping: 4 consecutive threads cover one 16-float k-row
    const int prow = t >> 2;          // 0..31
    const int pkq  = t & 3;

    // ---- stage qlog/klog into smem (ordinary LDG; visible after 1st sync) ----
    {
        float* ql = (float*)(smc + SM_QLOG);
        float* kl = (float*)(smc + SM_KLOG);
        ql[t] = g_qlog[bb * L_DIM + bm * BM + t];
        kl[t] = g_klog[bb * L_DIM + bn * BN + t];
    }

    auto issue_stage = [&](int c) {
        const int s = c % NSTAGE;
        const int koff = c * BK + pkq * 4;
        const uint32_t abase = sb + SM_TILES + s * STAGE_B;
        const uint32_t bbase = abase + A_STAGE_B;
        #pragma unroll
        for (int i = 0; i < 4; i++) {
            const int r = prow + 32 * i;
            cpa16(abase + (uint32_t)(r * SKA + pkq * 4) * 4,
                  Ag + (size_t)r * D_DIM + koff);
            cpa16(bbase + (uint32_t)(r * SKA + pkq * 4) * 4,
                  Bg + (size_t)r * D_DIM + koff);
        }
    };

    float acc[4][8][4];
    #pragma unroll
    for (int i = 0; i < 4; i++)
        #pragma unroll
        for (int j = 0; j < 8; j++)
            #pragma unroll
            for (int k2 = 0; k2 < 4; k2++)
                acc[i][j][k2] = 0.f;

    // ---- ldmatrix per-lane base offsets (within a stage) ----
    // A (x4): t0=(rows lo,+0) t1=(rows hi,+0) t2=(rows lo,+16B) t3=(hi,+16B)
    //   -> regs r0..r3 = a0,a1,a2,a3
    const int tA = lane >> 3, rA = lane & 7;
    const uint32_t aOff = (uint32_t)((wm * 64 + (tA & 1) * 8 + rA) * SKA) * 4
                        + (uint32_t)(tA >> 1) * 16;
    // B (x4): t0=(n lo,+0) t1=(n lo,+16B) t2=(n hi,+0) t3=(n hi,+16B)
    //   -> r0,r1 = b0,b1 of nf=2p ; r2,r3 = b0,b1 of nf=2p+1
    const uint32_t bOff = (uint32_t)((wn * 64 + (tA >> 1) * 8 + rA) * SKA) * 4
                        + (uint32_t)(tA & 1) * 16;

    // ---- prologue: fill 4 of 5 stages ----
    issue_stage(0); cpa_commit();
    issue_stage(1); cpa_commit();
    issue_stage(2); cpa_commit();
    issue_stage(3); cpa_commit();

    // Invariant: before the wait in iter c there are 4+c commits; wait_group 3
    // -> stage c complete. issue_stage(c+4) writes buffer (c+4)%5 == (c-1)%5,
    // whose reads completed before the __syncthreads at top of iter c.
    for (int c = 0; c < NKT; c++) {
        cpa_wait3();
        __syncthreads();

        if (c + 4 < NKT) issue_stage(c + 4);
        cpa_commit();

        const int s = c % NSTAGE;
        const uint32_t aBase = sb + SM_TILES + s * STAGE_B + aOff;
        const uint32_t bBase = sb + SM_TILES + s * STAGE_B + A_STAGE_B + bOff;

        // ---- batch ALL fragment loads for the tile (both ks) up front so
        //      ks1 LDSM latency hides under the ks0 MMA burst ----
        uint32_t afr[2][4][4], bfr[2][4][4];
        #pragma unroll
        for (int ks = 0; ks < 2; ks++) {
            const uint32_t kbyte = (uint32_t)ks * 32;
            #pragma unroll
            for (int mf = 0; mf < 4; mf++)
                ldsm4(afr[ks][mf], aBase + (uint32_t)(mf * 16 * SKA) * 4 + kbyte);
            #pragma unroll
            for (int p = 0; p < 4; p++)
                ldsm4(bfr[ks][p], bBase + (uint32_t)(p * 16 * SKA) * 4 + kbyte);
        }
        // A is raw fp32: round in place (alu, latency 4 — negligible)
        #pragma unroll
        for (int ks = 0; ks < 2; ks++)
            #pragma unroll
            for (int mf = 0; mf < 4; mf++)
                #pragma unroll
                for (int r = 0; r < 4; r++)
                    afr[ks][mf][r] =
                        __float_as_uint(to_tf32(__uint_as_float(afr[ks][mf][r])));
        // ---- 128 MMAs back-to-back ----
        #pragma unroll
        for (int ks = 0; ks < 2; ks++)
            #pragma unroll
            for (int mf = 0; mf < 4; mf++)
                #pragma unroll
                for (int p = 0; p < 4; p++) {
                    mma_tf32(acc[mf][2 * p    ], afr[ks][mf], &bfr[ks][p][0]);
                    mma_tf32(acc[mf][2 * p + 1], afr[ks][mf], &bfr[ks][p][2]);
                }
    }
    __syncthreads();

    // ---- epilogue: out = dot + qlog[q] + klog[k] ----
    const float* qlog_s = (const float*)(smc + SM_QLOG);
    const float* klog_s = (const float*)(smc + SM_KLOG);
    float* Ob = out + ((size_t)bb * L_DIM + (size_t)bm * BM) * L_DIM + (size_t)bn * BN;
    #pragma unroll
    for (int mf = 0; mf < 4; mf++) {
        const int mo    = wm * 64 + mf * 16;
        const float ql0 = qlog_s[mo + gr];
        const float ql1 = qlog_s[mo + gr + 8];
        #pragma unroll
        for (int nf = 0; nf < 8; nf++) {
            const int no    = wn * 64 + nf * 8 + 2 * gc;
            const float kl0 = klog_s[no];
            const float kl1 = klog_s[no + 1];
            float2 v0, v1;
            v0.x = acc[mf][nf][0] + ql0 + kl0;
            v0.y = acc[mf][nf][1] + ql0 + kl1;
            v1.x = acc[mf][nf][2] + ql1 + kl0;
            v1.y = acc[mf][nf][3] + ql1 + kl1;
            *reinterpret_cast<float2*>(Ob + (size_t)(mo + gr    ) * L_DIM + no) = v0;
            *reinterpret_cast<float2*>(Ob + (size_t)(mo + gr + 8) * L_DIM + no) = v1;
        }
    }
}

extern "C" void kernel_launch(void* const* d_in, const int* in_sizes, int n_in,
                              void* d_out, int out_size)
{
    const float* Q  = (const float*)d_in[0];
    const float* K  = (const float*)d_in[1];
    const float* w1 = (const float*)d_in[2];
    const float* w2 = (const float*)d_in[3];
    const float* w3 = (const float*)d_in[4];

    cudaFuncSetAttribute(trilinear_gemm,
                         cudaFuncAttributeMaxDynamicSharedMemorySize, SM_TOTAL);

    prepass_kernel<<<NROWS / 8, 256>>>(Q, K, w1, w2, w3);

    dim3 grid(L_DIM / BN, L_DIM / BM, 32);   // (8, 8, 32)
    trilinear_gemm<<<grid, THREADS, SM_TOTAL>>>(Q, (float*)d_out);
}